// round 4
// baseline (speedup 1.0000x reference)
#include <cuda_runtime.h>
#include <math.h>

// SpectralAngleLoss fused: B=8192 rows, N=256 peaks, 2000 bins.
// One warp per row, warp-private smem histogram (8KB), non-atomic scatter via
// __match_any_sync conflict resolution, gather-form norms/dot, last-block-done
// final reduction (deterministic, graph-replay safe).

#define N_PEAKS      256
#define NUM_BINS     2000
#define ROWS_PER_CTA 4
#define THREADS      128   // 4 warps
#define MAX_CTAS     4096

__device__ float        g_cta_partials[MAX_CTAS];
__device__ unsigned int g_count = 0;

__device__ __forceinline__ int mz_bin(float mz) {
    int b = (int)(mz * 2000.0f);          // trunc == astype(int32), mz >= 0
    return min(max(b, 0), NUM_BINS - 1);
}

__device__ __forceinline__ void scatter8(float* __restrict__ h,
                                         const int* b, const float* v, int lane) {
    #pragma unroll
    for (int k = 0; k < 8; k++) {
        int   bin = b[k];
        float val = v[k];
        unsigned m = __match_any_sync(0xFFFFFFFFu, bin);
        if (m == (1u << lane)) {
            h[bin] += val;                 // unique bin in this batch: plain RMW
        } else {
            atomicAdd(&h[bin], val);       // rare collision group
        }
    }
}

__global__ __launch_bounds__(THREADS)
void sal_fused(const float* __restrict__ pred_mz,
               const float* __restrict__ pred_int,
               const float* __restrict__ targ_mz,
               const float* __restrict__ targ_int,
               const float* __restrict__ targ_mask,
               float* __restrict__ out, int rows)
{
    __shared__ __align__(16) float hist[ROWS_PER_CTA][NUM_BINS];
    __shared__ float cta_ang[ROWS_PER_CTA];
    __shared__ float red[THREADS];
    __shared__ int   is_last;

    const int tid  = threadIdx.x;
    const int w    = tid >> 5;
    const int lane = tid & 31;
    const int row  = blockIdx.x * ROWS_PER_CTA + w;

    if (row < rows) {
        const int base4 = row * (N_PEAKS / 4);   // float4 index base
        float ip[8], itm[8];
        int   bp[8], bt[8];

        // ---- coalesced float4 loads; bins computed immediately, mz discarded
        {
            const float4* pmz = (const float4*)pred_mz   + base4;
            const float4* pin = (const float4*)pred_int  + base4;
            const float4* tmz = (const float4*)targ_mz   + base4;
            const float4* tin = (const float4*)targ_int  + base4;
            const float4* tms = (const float4*)targ_mask + base4;
            #pragma unroll
            for (int h = 0; h < 2; h++) {
                int i4 = lane + 32 * h;
                float4 a = pmz[i4];  float4 b = pin[i4];
                float4 c = tmz[i4];  float4 d = tin[i4];  float4 e = tms[i4];
                bp[4*h+0] = mz_bin(a.x); bp[4*h+1] = mz_bin(a.y);
                bp[4*h+2] = mz_bin(a.z); bp[4*h+3] = mz_bin(a.w);
                ip[4*h+0] = b.x; ip[4*h+1] = b.y; ip[4*h+2] = b.z; ip[4*h+3] = b.w;
                bt[4*h+0] = mz_bin(c.x); bt[4*h+1] = mz_bin(c.y);
                bt[4*h+2] = mz_bin(c.z); bt[4*h+3] = mz_bin(c.w);
                itm[4*h+0] = d.x * e.x; itm[4*h+1] = d.y * e.y;
                itm[4*h+2] = d.z * e.z; itm[4*h+3] = d.w * e.w;
            }
        }

        float* h = hist[w];
        float4* h4 = (float4*)h;                 // 500 float4 = 8000B, 16B aligned

        // ---- zero, scatter TARGET, gather tn^2 and dot
        {
            float4 z = make_float4(0.f, 0.f, 0.f, 0.f);
            for (int i = lane; i < NUM_BINS / 4; i += 32) h4[i] = z;
        }
        scatter8(h, bt, itm, lane);

        float dot = 0.f, tn = 0.f, pn = 0.f;
        #pragma unroll
        for (int k = 0; k < 8; k++) tn  = fmaf(itm[k], h[bt[k]], tn);
        #pragma unroll
        for (int k = 0; k < 8; k++) dot = fmaf(ip[k],  h[bp[k]], dot);

        // ---- re-zero, scatter PRED, gather pn^2
        {
            float4 z = make_float4(0.f, 0.f, 0.f, 0.f);
            for (int i = lane; i < NUM_BINS / 4; i += 32) h4[i] = z;
        }
        scatter8(h, bp, ip, lane);
        #pragma unroll
        for (int k = 0; k < 8; k++) pn  = fmaf(ip[k], h[bp[k]], pn);

        // ---- warp reduce 3 scalars
        #pragma unroll
        for (int o = 16; o > 0; o >>= 1) {
            dot += __shfl_xor_sync(0xFFFFFFFFu, dot, o);
            tn  += __shfl_xor_sync(0xFFFFFFFFu, tn,  o);
            pn  += __shfl_xor_sync(0xFFFFFFFFu, pn,  o);
        }
        if (lane == 0) {
            const float eps = 1e-8f;
            float denom = fmaxf(sqrtf(pn), eps) * fmaxf(sqrtf(tn), eps);
            float c = dot / denom;
            c = fminf(fmaxf(c, -1.0f), 1.0f);
            cta_ang[w] = acosf(c);
        }
    } else if (lane == 0) {
        cta_ang[w] = 0.f;
    }
    __syncthreads();

    // ---- one partial per CTA, then last-block-done final reduction
    if (tid == 0) {
        float s = 0.f;
        #pragma unroll
        for (int i = 0; i < ROWS_PER_CTA; i++) s += cta_ang[i];
        g_cta_partials[blockIdx.x] = s;
        __threadfence();
        unsigned old = atomicAdd(&g_count, 1u);
        is_last = (old == gridDim.x - 1) ? 1 : 0;
    }
    __syncthreads();

    if (is_last) {
        int nb = gridDim.x;
        float v = 0.f;
        for (int i = tid; i < nb; i += THREADS) v += g_cta_partials[i];
        red[tid] = v;
        __syncthreads();
        #pragma unroll
        for (int o = THREADS / 2; o > 0; o >>= 1) {
            if (tid < o) red[tid] += red[tid + o];
            __syncthreads();
        }
        if (tid == 0) {
            out[0] = red[0] / ((float)rows * 3.14159265358979323846f);
            g_count = 0;                  // reset for next graph replay
        }
    }
}

extern "C" void kernel_launch(void* const* d_in, const int* in_sizes, int n_in,
                              void* d_out, int out_size)
{
    const float* pred_mz   = (const float*)d_in[0];
    const float* pred_int  = (const float*)d_in[1];
    const float* targ_mz   = (const float*)d_in[2];
    const float* targ_int  = (const float*)d_in[3];
    const float* targ_mask = (const float*)d_in[4];
    float* out = (float*)d_out;

    int rows = in_sizes[0] / N_PEAKS;
    int grid = (rows + ROWS_PER_CTA - 1) / ROWS_PER_CTA;
    if (grid > MAX_CTAS) grid = MAX_CTAS;

    sal_fused<<<grid, THREADS>>>(pred_mz, pred_int, targ_mz, targ_int, targ_mask,
                                 out, rows);
}

// round 5
// speedup vs baseline: 1.2486x; 1.2486x over previous
#include <cuda_runtime.h>
#include <math.h>

// SpectralAngleLoss A/B: rows split between two scatter strategies.
//   A: block-per-row, 256 thr, shared-atomic scatter (known ~2cyc/atomic-lane floor)
//   B: warp-per-row, match_any + plain RMW scatter (non-atomic path)
// B's last CTA does the fused final mean (last-block-done, graph-replay safe).

#define N_PEAKS   256
#define NUM_BINS  2000
#define NB_PAD    2048          // padded bin array (power of 2, exact unroll)
#define MAX_ROWS  8192

__device__ float        g_partials[MAX_ROWS];
__device__ unsigned int g_count = 0;

__device__ __forceinline__ int mz_bin(float mz) {
    int b = (int)(mz * 2000.0f);            // trunc toward zero == astype(int32)
    return min(max(b, 0), NUM_BINS - 1);
}

// ─────────────────────────────────────────────────────────────────────────────
// Kernel A: R1-style atomic scatter, one row per 256-thread CTA.
// ─────────────────────────────────────────────────────────────────────────────
__global__ __launch_bounds__(256)
void sal_atomic(const float* __restrict__ pred_mz,
                const float* __restrict__ pred_int,
                const float* __restrict__ targ_mz,
                const float* __restrict__ targ_int,
                const float* __restrict__ targ_mask,
                int row0)
{
    __shared__ __align__(16) float ph[NB_PAD];
    __shared__ __align__(16) float th[NB_PAD];
    __shared__ float red[3][8];

    const int row = row0 + blockIdx.x;
    const int tid = threadIdx.x;

    {
        float4 z = make_float4(0.f, 0.f, 0.f, 0.f);
        float4* p4 = (float4*)ph;
        float4* t4 = (float4*)th;
        #pragma unroll
        for (int i = 0; i < NB_PAD / 4 / 256; i++) {   // 2 iters exact
            p4[tid + i * 256] = z;
            t4[tid + i * 256] = z;
        }
    }
    __syncthreads();

    const int idx = row * N_PEAKS + tid;
    {
        float ip = pred_int[idx];
        int bp = mz_bin(pred_mz[idx]);
        atomicAdd(&ph[bp], ip);

        float it = targ_int[idx] * targ_mask[idx];
        int bt = mz_bin(targ_mz[idx]);
        atomicAdd(&th[bt], it);
    }
    __syncthreads();

    float dot = 0.f, pn = 0.f, tn = 0.f;
    #pragma unroll
    for (int i = 0; i < NB_PAD / 256; i++) {           // 8 iters exact
        float p = ph[tid + i * 256];
        float t = th[tid + i * 256];
        dot = fmaf(p, t, dot);
        pn  = fmaf(p, p, pn);
        tn  = fmaf(t, t, tn);
    }
    #pragma unroll
    for (int o = 16; o > 0; o >>= 1) {
        dot += __shfl_xor_sync(0xFFFFFFFFu, dot, o);
        pn  += __shfl_xor_sync(0xFFFFFFFFu, pn,  o);
        tn  += __shfl_xor_sync(0xFFFFFFFFu, tn,  o);
    }
    if ((tid & 31) == 0) {
        int w = tid >> 5;
        red[0][w] = dot; red[1][w] = pn; red[2][w] = tn;
    }
    __syncthreads();
    if (tid == 0) {
        float d = 0.f, a = 0.f, b = 0.f;
        #pragma unroll
        for (int w = 0; w < 8; w++) { d += red[0][w]; a += red[1][w]; b += red[2][w]; }
        const float eps = 1e-8f;
        float c = d / (fmaxf(sqrtf(a), eps) * fmaxf(sqrtf(b), eps));
        c = fminf(fmaxf(c, -1.0f), 1.0f);
        g_partials[row] = acosf(c);
    }
}

// ─────────────────────────────────────────────────────────────────────────────
// Kernel B: warp-per-row, match_any conflict resolution, gather-form norms.
// Last CTA performs the fused global mean.
// ─────────────────────────────────────────────────────────────────────────────
#define B_ROWS_PER_CTA 4
#define B_THREADS      128

__device__ __forceinline__ void scatter8(float* __restrict__ h,
                                         const int* b, const float* v, int lane) {
    #pragma unroll
    for (int k = 0; k < 8; k++) {
        int   bin = b[k];
        float val = v[k];
        unsigned m = __match_any_sync(0xFFFFFFFFu, bin);
        if (m == (1u << lane)) h[bin] += val;     // unique in batch: plain RMW
        else                   atomicAdd(&h[bin], val);
    }
}

__global__ __launch_bounds__(B_THREADS)
void sal_rmw(const float* __restrict__ pred_mz,
             const float* __restrict__ pred_int,
             const float* __restrict__ targ_mz,
             const float* __restrict__ targ_int,
             const float* __restrict__ targ_mask,
             float* __restrict__ out,
             int row0, int rows_total)
{
    __shared__ __align__(16) float hist[B_ROWS_PER_CTA][NB_PAD];
    __shared__ float red[B_THREADS];
    __shared__ int   is_last;

    const int tid  = threadIdx.x;
    const int w    = tid >> 5;
    const int lane = tid & 31;
    const int row  = row0 + blockIdx.x * B_ROWS_PER_CTA + w;

    if (row < rows_total) {
        const int base4 = row * (N_PEAKS / 4);
        float ip[8], itm[8];
        int   bp[8], bt[8];
        {
            const float4* pmz = (const float4*)pred_mz   + base4;
            const float4* pin = (const float4*)pred_int  + base4;
            const float4* tmz = (const float4*)targ_mz   + base4;
            const float4* tin = (const float4*)targ_int  + base4;
            const float4* tms = (const float4*)targ_mask + base4;
            #pragma unroll
            for (int g = 0; g < 2; g++) {
                int i4 = lane + 32 * g;
                float4 a = pmz[i4]; float4 b = pin[i4];
                float4 c = tmz[i4]; float4 d = tin[i4]; float4 e = tms[i4];
                bp[4*g+0]=mz_bin(a.x); bp[4*g+1]=mz_bin(a.y); bp[4*g+2]=mz_bin(a.z); bp[4*g+3]=mz_bin(a.w);
                ip[4*g+0]=b.x; ip[4*g+1]=b.y; ip[4*g+2]=b.z; ip[4*g+3]=b.w;
                bt[4*g+0]=mz_bin(c.x); bt[4*g+1]=mz_bin(c.y); bt[4*g+2]=mz_bin(c.z); bt[4*g+3]=mz_bin(c.w);
                itm[4*g+0]=d.x*e.x; itm[4*g+1]=d.y*e.y; itm[4*g+2]=d.z*e.z; itm[4*g+3]=d.w*e.w;
            }
        }

        float* h  = hist[w];
        float4* h4 = (float4*)h;
        {
            float4 z = make_float4(0.f,0.f,0.f,0.f);
            #pragma unroll
            for (int i = 0; i < NB_PAD / 4 / 32; i++) h4[lane + i * 32] = z;  // 16 exact
        }
        __syncwarp();
        scatter8(h, bt, itm, lane);
        __syncwarp();

        float dot = 0.f, tn = 0.f, pn = 0.f;
        #pragma unroll
        for (int k = 0; k < 8; k++) tn  = fmaf(itm[k], h[bt[k]], tn);
        #pragma unroll
        for (int k = 0; k < 8; k++) dot = fmaf(ip[k],  h[bp[k]], dot);
        __syncwarp();
        {
            float4 z = make_float4(0.f,0.f,0.f,0.f);
            #pragma unroll
            for (int i = 0; i < NB_PAD / 4 / 32; i++) h4[lane + i * 32] = z;
        }
        __syncwarp();
        scatter8(h, bp, ip, lane);
        __syncwarp();
        #pragma unroll
        for (int k = 0; k < 8; k++) pn = fmaf(ip[k], h[bp[k]], pn);

        #pragma unroll
        for (int o = 16; o > 0; o >>= 1) {
            dot += __shfl_xor_sync(0xFFFFFFFFu, dot, o);
            tn  += __shfl_xor_sync(0xFFFFFFFFu, tn,  o);
            pn  += __shfl_xor_sync(0xFFFFFFFFu, pn,  o);
        }
        if (lane == 0) {
            const float eps = 1e-8f;
            float c = dot / (fmaxf(sqrtf(pn), eps) * fmaxf(sqrtf(tn), eps));
            c = fminf(fmaxf(c, -1.0f), 1.0f);
            g_partials[row] = acosf(c);
        }
    }
    __syncthreads();

    // ---- fused final mean: last CTA of kernel B reduces everything
    if (tid == 0) {
        __threadfence();
        unsigned old = atomicAdd(&g_count, 1u);
        is_last = (old == gridDim.x - 1) ? 1 : 0;
    }
    __syncthreads();
    if (is_last) {
        float v = 0.f;
        for (int i = tid; i < rows_total; i += B_THREADS) v += g_partials[i];
        red[tid] = v;
        __syncthreads();
        #pragma unroll
        for (int o = B_THREADS / 2; o > 0; o >>= 1) {
            if (tid < o) red[tid] += red[tid + o];
            __syncthreads();
        }
        if (tid == 0) {
            out[0] = red[0] / ((float)rows_total * 3.14159265358979323846f);
            g_count = 0;                        // reset for next graph replay
        }
    }
}

// ─────────────────────────────────────────────────────────────────────────────
extern "C" void kernel_launch(void* const* d_in, const int* in_sizes, int n_in,
                              void* d_out, int out_size)
{
    const float* pred_mz   = (const float*)d_in[0];
    const float* pred_int  = (const float*)d_in[1];
    const float* targ_mz   = (const float*)d_in[2];
    const float* targ_int  = (const float*)d_in[3];
    const float* targ_mask = (const float*)d_in[4];
    float* out = (float*)d_out;

    int rows = in_sizes[0] / N_PEAKS;
    if (rows > MAX_ROWS) rows = MAX_ROWS;
    int rowsA = rows / 2;                                  // atomic half
    int rowsB = rows - rowsA;                              // RMW half
    int gridB = (rowsB + B_ROWS_PER_CTA - 1) / B_ROWS_PER_CTA;

    sal_atomic<<<rowsA, 256>>>(pred_mz, pred_int, targ_mz, targ_int, targ_mask, 0);
    sal_rmw<<<gridB, B_THREADS>>>(pred_mz, pred_int, targ_mz, targ_int, targ_mask,
                                  out, rowsA, rows);
}

// round 6
// speedup vs baseline: 1.8789x; 1.5048x over previous
#include <cuda_runtime.h>
#include <math.h>

// SpectralAngleLoss: all-atomic scatter (measured fastest path), gather-form
// norms (no bin scan), fused last-block mean. B=8192 rows, N=256, 2000 bins.

#define N_PEAKS   256
#define NUM_BINS  2000
#define NB_PAD    2048
#define MAX_ROWS  8192
#define THREADS   256

__device__ float        g_partials[MAX_ROWS];
__device__ unsigned int g_count = 0;

__device__ __forceinline__ int mz_bin(float mz) {
    int b = (int)(mz * 2000.0f);           // trunc toward zero == astype(int32)
    return min(max(b, 0), NUM_BINS - 1);
}

__global__ __launch_bounds__(THREADS)
void sal_kernel(const float* __restrict__ pred_mz,
                const float* __restrict__ pred_int,
                const float* __restrict__ targ_mz,
                const float* __restrict__ targ_int,
                const float* __restrict__ targ_mask,
                float* __restrict__ out, int rows)
{
    __shared__ __align__(16) float ph[NB_PAD];
    __shared__ __align__(16) float th[NB_PAD];
    __shared__ float red[3][THREADS / 32];
    __shared__ float fred[THREADS];
    __shared__ int   is_last;

    const int row = blockIdx.x;
    const int tid = threadIdx.x;

    // ---- zero both histograms (4 STS.128 per thread, exact)
    {
        float4 z = make_float4(0.f, 0.f, 0.f, 0.f);
        float4* p4 = (float4*)ph;
        float4* t4 = (float4*)th;
        #pragma unroll
        for (int i = 0; i < NB_PAD / 4 / THREADS; i++) {   // 2 iters
            p4[tid + i * THREADS] = z;
            t4[tid + i * THREADS] = z;
        }
    }

    // ---- loads (coalesced, start before the barrier retires dependence)
    const int idx = row * N_PEAKS + tid;
    const float mzp = pred_mz[idx];
    const float ip  = pred_int[idx];
    const float mzt = targ_mz[idx];
    const float it  = targ_int[idx];
    const float ms  = targ_mask[idx];

    const int   bp  = mz_bin(mzp);
    const int   bt  = mz_bin(mzt);
    const float itm = it * ms;

    __syncthreads();

    // ---- scatter (the measured bottleneck: 2 spread ATOMS per thread)
    atomicAdd(&ph[bp], ip);
    atomicAdd(&th[bt], itm);
    __syncthreads();

    // ---- gather-form reductions: 3 LDS per thread, no bin scan
    float dot = ip  * th[bp];
    float pn  = ip  * ph[bp];
    float tn  = itm * th[bt];

    #pragma unroll
    for (int o = 16; o > 0; o >>= 1) {
        dot += __shfl_xor_sync(0xFFFFFFFFu, dot, o);
        pn  += __shfl_xor_sync(0xFFFFFFFFu, pn,  o);
        tn  += __shfl_xor_sync(0xFFFFFFFFu, tn,  o);
    }
    if ((tid & 31) == 0) {
        int w = tid >> 5;
        red[0][w] = dot; red[1][w] = pn; red[2][w] = tn;
    }
    __syncthreads();

    if (tid == 0) {
        float d = 0.f, a = 0.f, b = 0.f;
        #pragma unroll
        for (int w = 0; w < THREADS / 32; w++) {
            d += red[0][w]; a += red[1][w]; b += red[2][w];
        }
        const float eps = 1e-8f;
        float c = d / (fmaxf(sqrtf(a), eps) * fmaxf(sqrtf(b), eps));
        c = fminf(fmaxf(c, -1.0f), 1.0f);
        g_partials[row] = acosf(c);
        __threadfence();
        unsigned old = atomicAdd(&g_count, 1u);
        is_last = (old == (unsigned)gridDim.x - 1u) ? 1 : 0;
    }
    __syncthreads();

    // ---- fused final mean in the last-arriving CTA (deterministic order)
    if (is_last) {
        const float4* gp4 = (const float4*)g_partials;
        float v = 0.f;
        #pragma unroll
        for (int i = 0; i < MAX_ROWS / 4 / THREADS; i++) {  // 8 iters
            float4 a4 = gp4[tid + i * THREADS];
            v += (a4.x + a4.y) + (a4.z + a4.w);
        }
        fred[tid] = v;
        __syncthreads();
        #pragma unroll
        for (int o = THREADS / 2; o > 0; o >>= 1) {
            if (tid < o) fred[tid] += fred[tid + o];
            __syncthreads();
        }
        if (tid == 0) {
            out[0] = fred[0] / ((float)rows * 3.14159265358979323846f);
            g_count = 0;                     // reset for next graph replay
        }
    }
}

extern "C" void kernel_launch(void* const* d_in, const int* in_sizes, int n_in,
                              void* d_out, int out_size)
{
    const float* pred_mz   = (const float*)d_in[0];
    const float* pred_int  = (const float*)d_in[1];
    const float* targ_mz   = (const float*)d_in[2];
    const float* targ_int  = (const float*)d_in[3];
    const float* targ_mask = (const float*)d_in[4];
    float* out = (float*)d_out;

    int rows = in_sizes[0] / N_PEAKS;
    if (rows > MAX_ROWS) rows = MAX_ROWS;

    sal_kernel<<<rows, THREADS>>>(pred_mz, pred_int, targ_mz, targ_int,
                                  targ_mask, out, rows);
}